// round 17
// baseline (speedup 1.0000x reference)
#include <cuda_runtime.h>
#include <cuda_fp16.h>
#include <math.h>
#include <stdint.h>

// ---------------------------------------------------------------------------
// Problem constants: B=2, S=2048, D=1024, H=16, dh=64
// ---------------------------------------------------------------------------
#define B_  2
#define S_  2048
#define D_  1024
#define H_  16
#define DH_ 64
#define M_TOK (B_ * S_)          // 4096 tokens

// Scratch (fp16 operands)
__device__ __half g_x[M_TOK * D_];
__device__ __half g_wqkv[D_ * 3 * D_];      // w_qkv [D][3D] = [k][n]
__device__ __half g_wout[D_ * D_];          // w_out [D][D]  = [k][n]
__device__ __half g_qkv[M_TOK * 3 * D_];    // Q columns pre-scaled by 0.125*log2(e)
__device__ __half g_attn[M_TOK * D_];

// ---------------------------------------------------------------------------
// Helpers
// ---------------------------------------------------------------------------
__device__ __forceinline__ uint32_t smem_u32(const void* p) {
    return (uint32_t)__cvta_generic_to_shared(p);
}
__device__ __forceinline__ void cp_async16(uint32_t dst, const void* src) {
    asm volatile("cp.async.cg.shared.global [%0], [%1], 16;\n" :: "r"(dst), "l"(src));
}
__device__ __forceinline__ void cp_commit() {
    asm volatile("cp.async.commit_group;\n" ::: "memory");
}
template <int N>
__device__ __forceinline__ void cp_wait() {
    asm volatile("cp.async.wait_group %0;\n" :: "n"(N) : "memory");
}
// fp16 m16n8k16 mma, fp32 accumulate
__device__ __forceinline__ void mma_f16(
    float* c, uint32_t a0, uint32_t a1, uint32_t a2, uint32_t a3,
    uint32_t b0, uint32_t b1)
{
    asm volatile(
        "mma.sync.aligned.m16n8k16.row.col.f32.f16.f16.f32 "
        "{%0,%1,%2,%3}, {%4,%5,%6,%7}, {%8,%9}, {%0,%1,%2,%3};\n"
        : "+f"(c[0]), "+f"(c[1]), "+f"(c[2]), "+f"(c[3])
        : "r"(a0), "r"(a1), "r"(a2), "r"(a3), "r"(b0), "r"(b1));
}
// fp16 m16n8k16 mma, fp16 accumulate (possible 2x rate on legacy HMMA path)
__device__ __forceinline__ void mma_f16acc(
    uint32_t* c, uint32_t a0, uint32_t a1, uint32_t a2, uint32_t a3,
    uint32_t b0, uint32_t b1)
{
    asm volatile(
        "mma.sync.aligned.m16n8k16.row.col.f16.f16.f16.f16 "
        "{%0,%1}, {%2,%3,%4,%5}, {%6,%7}, {%0,%1};\n"
        : "+r"(c[0]), "+r"(c[1])
        : "r"(a0), "r"(a1), "r"(a2), "r"(a3), "r"(b0), "r"(b1));
}
__device__ __forceinline__ uint32_t h2_u32(__half2 h) {
    return *reinterpret_cast<uint32_t*>(&h);
}
__device__ __forceinline__ void ldsm_x4(uint32_t* r, uint32_t addr) {
    asm volatile("ldmatrix.sync.aligned.m8n8.x4.shared.b16 {%0,%1,%2,%3}, [%4];"
        : "=r"(r[0]), "=r"(r[1]), "=r"(r[2]), "=r"(r[3]) : "r"(addr));
}
__device__ __forceinline__ void ldsm_x4_t(uint32_t* r, uint32_t addr) {
    asm volatile("ldmatrix.sync.aligned.m8n8.x4.trans.shared.b16 {%0,%1,%2,%3}, [%4];"
        : "=r"(r[0]), "=r"(r[1]), "=r"(r[2]), "=r"(r[3]) : "r"(addr));
}

// ---------------------------------------------------------------------------
// Fused elementwise fp32 -> fp16 for x, w_qkv, w_out (one launch)
// ---------------------------------------------------------------------------
#define N4_X   (M_TOK * D_ / 4)
#define N4_WQ  (D_ * 3 * D_ / 4)
#define N4_WO  (D_ * D_ / 4)
#define N4_ALL (N4_X + N4_WQ + N4_WO)

__global__ void cvt_all_kernel(const float* __restrict__ x,
                               const float* __restrict__ wq,
                               const float* __restrict__ wo,
                               __half* __restrict__ xh,
                               __half* __restrict__ wqh,
                               __half* __restrict__ woh)
{
    for (int i = blockIdx.x * blockDim.x + threadIdx.x; i < N4_ALL;
         i += gridDim.x * blockDim.x) {
        const float* in;
        __half* out;
        int j = i;
        if (j < N4_X)                { in = x;  out = xh; }
        else if ((j -= N4_X) < N4_WQ){ in = wq; out = wqh; }
        else { j -= N4_WQ;             in = wo; out = woh; }
        float4 v = ((const float4*)in)[j];
        ((__half2*)out)[2 * j]     = __floats2half2_rn(v.x, v.y);
        ((__half2*)out)[2 * j + 1] = __floats2half2_rn(v.z, v.w);
    }
}

// ---------------------------------------------------------------------------
// fp16 GEMM: C = A @ W, A[M][K] row-major, W[K][N] row-major, ldmatrix loads.
// F16ACC: accumulate in fp16 C fragments within each 64-K stage, promote to
// fp32 once per stage (probe: fp16-acc HMMA may run 2x on the legacy path).
// ---------------------------------------------------------------------------
#define GBM 128
#define GBN 128
#define GBK 64
#define AST 72
#define BST 136
#define A_BUF (128 * AST)
#define B_BUF (64 * BST)
#define GEMM_SMEM (2 * (A_BUF + B_BUF) * 2)  // 71680 bytes
#define SCALE_LOG2E 0.1803368801111244f

template <bool F16ACC>
__global__ __launch_bounds__(256, 2) void gemm_f16_kernel(
    const __half* __restrict__ A, const __half* __restrict__ W,
    float* __restrict__ Cf, __half* __restrict__ Ch,
    int M, int N, int K, int scaleq)
{
    extern __shared__ __half smh[];
    const uint32_t smem_base = smem_u32(smh);

    const int tid  = threadIdx.x;
    const int warp = tid >> 5;
    const int lane = tid & 31;
    const int g    = lane >> 2;
    const int tg   = lane & 3;

    const int bm = blockIdx.y * GBM;
    const int bn = blockIdx.x * GBN;
    const int wm = (warp & 3) * 32;
    const int wn = (warp >> 2) * 64;

    const int arow = lane & 15;
    const int acol = (lane >> 4) << 3;
    const int trow = (lane & 7) + (((lane >> 3) & 1) << 3);
    const int tcol = (lane >> 4) << 3;

    float c[2][8][4];
#pragma unroll
    for (int mt = 0; mt < 2; mt++)
#pragma unroll
        for (int nt = 0; nt < 8; nt++)
#pragma unroll
            for (int i = 0; i < 4; i++) c[mt][nt][i] = 0.f;

    auto load_stage = [&](int k0, int s) {
        const uint32_t abase = smem_base + (uint32_t)(s * (A_BUF + B_BUF)) * 2;
        const uint32_t bbase = abase + (uint32_t)A_BUF * 2;
#pragma unroll
        for (int it = 0; it < 4; ++it) {
            int idx = tid + it * 256;
            int r = idx >> 3, cc = idx & 7;
            cp_async16(abase + (uint32_t)(r * AST + cc * 8) * 2,
                       A + (size_t)(bm + r) * K + k0 + cc * 8);
        }
#pragma unroll
        for (int it = 0; it < 4; ++it) {
            int idx = tid + it * 256;
            int r = idx >> 4, cc = idx & 15;
            cp_async16(bbase + (uint32_t)(r * BST + cc * 8) * 2,
                       W + (size_t)(k0 + r) * N + bn + cc * 8);
        }
        cp_commit();
    };

    load_stage(0, 0);

    const int n_k = K / GBK;              // 16
    for (int kt = 0; kt < n_k; ++kt) {
        const int buf = kt & 1;
        if (kt + 1 < n_k) {
            load_stage((kt + 1) * GBK, buf ^ 1);
            cp_wait<1>();
        } else {
            cp_wait<0>();
        }
        __syncthreads();

        const uint32_t Ab = smem_base + (uint32_t)(buf * (A_BUF + B_BUF)) * 2;
        const uint32_t Bb = Ab + (uint32_t)A_BUF * 2;

        uint32_t hc[2][8][2];
        if (F16ACC) {
#pragma unroll
            for (int mt = 0; mt < 2; mt++)
#pragma unroll
                for (int nt = 0; nt < 8; nt++) { hc[mt][nt][0] = 0u; hc[mt][nt][1] = 0u; }
        }

#pragma unroll
        for (int kk = 0; kk < 4; ++kk) {
            const int ko = kk * 16;
            uint32_t a[2][4];
#pragma unroll
            for (int mt = 0; mt < 2; mt++) {
                ldsm_x4(a[mt], Ab + (uint32_t)((wm + mt * 16 + arow) * AST
                                               + ko + acol) * 2);
            }
#pragma unroll
            for (int ntp = 0; ntp < 4; ntp++) {
                uint32_t bb[4];
                ldsm_x4_t(bb, Bb + (uint32_t)((ko + trow) * BST
                                              + wn + ntp * 16 + tcol) * 2);
#pragma unroll
                for (int mt = 0; mt < 2; mt++) {
                    if (F16ACC) {
                        mma_f16acc(hc[mt][2 * ntp],     a[mt][0], a[mt][1], a[mt][2], a[mt][3], bb[0], bb[1]);
                        mma_f16acc(hc[mt][2 * ntp + 1], a[mt][0], a[mt][1], a[mt][2], a[mt][3], bb[2], bb[3]);
                    } else {
                        mma_f16(c[mt][2 * ntp],     a[mt][0], a[mt][1], a[mt][2], a[mt][3], bb[0], bb[1]);
                        mma_f16(c[mt][2 * ntp + 1], a[mt][0], a[mt][1], a[mt][2], a[mt][3], bb[2], bb[3]);
                    }
                }
            }
        }
        if (F16ACC) {
            // promote stage partials to fp32
#pragma unroll
            for (int mt = 0; mt < 2; mt++)
#pragma unroll
                for (int nt = 0; nt < 8; nt++) {
                    float2 lo = __half22float2(*(__half2*)&hc[mt][nt][0]);
                    float2 hi = __half22float2(*(__half2*)&hc[mt][nt][1]);
                    c[mt][nt][0] += lo.x; c[mt][nt][1] += lo.y;
                    c[mt][nt][2] += hi.x; c[mt][nt][3] += hi.y;
                }
        }
        __syncthreads();
    }

#pragma unroll
    for (int mt = 0; mt < 2; mt++) {
        const int r0 = bm + wm + mt * 16 + g;
#pragma unroll
        for (int nt = 0; nt < 8; nt++) {
            const int col = bn + wn + nt * 8 + tg * 2;
            if (Cf) {
                *(float2*)&Cf[(size_t)r0 * N + col] =
                    make_float2(c[mt][nt][0], c[mt][nt][1]);
                *(float2*)&Cf[(size_t)(r0 + 8) * N + col] =
                    make_float2(c[mt][nt][2], c[mt][nt][3]);
            } else {
                const float sc = (scaleq && col < D_) ? SCALE_LOG2E : 1.f;
                *(__half2*)&Ch[(size_t)r0 * N + col] =
                    __floats2half2_rn(c[mt][nt][0] * sc, c[mt][nt][1] * sc);
                *(__half2*)&Ch[(size_t)(r0 + 8) * N + col] =
                    __floats2half2_rn(c[mt][nt][2] * sc, c[mt][nt][3] * sc);
            }
        }
    }
}

// ---------------------------------------------------------------------------
// Flash attention v10: as R16 plus warp-level skip of fully-masked tiles
// (warps with wm<64 skip the compute of the last diagonal tile entirely;
// loads and barriers still execute on all warps).
// ---------------------------------------------------------------------------
#define AT_Q 128
#define AT_K 64
#define HS 72
#define NBUF 5
#define K_OFF 0
#define K_BUF (64 * HS)
#define V_OFF (NBUF * K_BUF)
#define V_BUF (64 * HS)
#define ATTN_SMEM ((NBUF * K_BUF + NBUF * V_BUF) * 2)   // 92160 bytes
#define NEG_INF_F (-1e30f)

__global__ __launch_bounds__(256, 2) void attn_kernel(
    const __half* __restrict__ qkv,
    __half* __restrict__ attn)
{
    const int qt   = (int)gridDim.x - 1 - (int)blockIdx.x;  // heavy first
    const int h    = blockIdx.y;
    const int b    = blockIdx.z;
    const int tid  = threadIdx.x;
    const int warp = tid >> 5;
    const int lane = tid & 31;
    const int g    = lane >> 2;
    const int tg   = lane & 3;
    const int wm   = warp * 16;

    extern __shared__ __half smh[];
    const uint32_t smem_base = smem_u32(smh);

    const int btok = b * S_;

    auto load_tile = [&](int kt, int s) {
#pragma unroll
        for (int it = 0; it < 4; ++it) {
            int idx = tid + it * 256;
            int sel = idx >> 9;              // 0:K  1:V
            int r   = (idx >> 3) & 63;
            int cc  = idx & 7;
            const __half* src = qkv
                + (size_t)(btok + kt * AT_K + r) * (3 * D_)
                + (sel ? 2 * D_ : D_) + h * DH_ + cc * 8;
            uint32_t dst = smem_base
                + (uint32_t)((sel ? V_OFF : K_OFF) + s * (sel ? V_BUF : K_BUF)
                             + r * HS + cc * 8) * 2;
            cp_async16(dst, src);
        }
        cp_commit();
    };

    const int n_tiles = 2 * qt + 2;
    load_tile(0, 0);
    if (1 < n_tiles) load_tile(1, 1);
    if (2 < n_tiles) load_tile(2, 2);

    uint32_t qa[4][4];
    {
        const size_t r0 = (size_t)(btok + qt * AT_Q + wm + g) * (3 * D_) + h * DH_;
        const size_t r1 = r0 + (size_t)8 * (3 * D_);
#pragma unroll
        for (int s4 = 0; s4 < 4; s4++) {
            const int ko = s4 * 16 + 2 * tg;
            qa[s4][0] = *(const uint32_t*)(qkv + r0 + ko);
            qa[s4][1] = *(const uint32_t*)(qkv + r1 + ko);
            qa[s4][2] = *(const uint32_t*)(qkv + r0 + ko + 8);
            qa[s4][3] = *(const uint32_t*)(qkv + r1 + ko + 8);
        }
    }

    const int krow = (lane & 7) + ((lane >> 4) << 3);
    const int kcol = ((lane >> 3) & 1) << 3;
    const int vrow = (lane & 7) + (((lane >> 3) & 1) << 3);
    const int vcol = (lane >> 4) << 3;

    // last key index this warp can see (causal): qt*128 + wm + 15
    const int last_key = qt * AT_Q + wm + 15;

    float o[8][4];
    float lsum0 = 0.f, lsum1 = 0.f;
#pragma unroll
    for (int nt = 0; nt < 8; nt++)
#pragma unroll
        for (int i = 0; i < 4; i++) o[nt][i] = 0.f;

    int buf = 0;
    for (int kt = 0; kt < n_tiles; ++kt) {
        const int rem = n_tiles - 1 - kt;
        if (rem >= 2)      cp_wait<2>();
        else if (rem == 1) cp_wait<1>();
        else               cp_wait<0>();
        if ((kt & 1) == 0) __syncthreads();

        if (kt + 3 < n_tiles) {
            int nb = buf + 3; if (nb >= NBUF) nb -= NBUF;
            load_tile(kt + 3, nb);
        }

        // warp-level skip: tile entirely above this warp's causal horizon
        if (kt * AT_K <= last_key) {
            const uint32_t Kb = smem_base + (uint32_t)(K_OFF + buf * K_BUF) * 2;
            const uint32_t Vb = smem_base + (uint32_t)(V_OFF + buf * V_BUF) * 2;

            // ---- S = Q @ K^T (log2 domain) ----
            float s[8][4];
#pragma unroll
            for (int nt = 0; nt < 8; nt++)
#pragma unroll
                for (int i = 0; i < 4; i++) s[nt][i] = 0.f;

#pragma unroll
            for (int s4 = 0; s4 < 4; s4++) {
                const int ko = s4 * 16;
#pragma unroll
                for (int ntp = 0; ntp < 4; ntp++) {
                    uint32_t kb[4];
                    ldsm_x4(kb, Kb + (uint32_t)((ntp * 16 + krow) * HS + ko + kcol) * 2);
                    mma_f16(s[2 * ntp],     qa[s4][0], qa[s4][1], qa[s4][2], qa[s4][3], kb[0], kb[1]);
                    mma_f16(s[2 * ntp + 1], qa[s4][0], qa[s4][1], qa[s4][2], qa[s4][3], kb[2], kb[3]);
                }
            }

            // ---- causal mask (diagonal tiles only) ----
            const bool interior = (kt * AT_K + AT_K - 1 <= qt * AT_Q + wm);
            if (!interior) {
                const int grow0 = qt * AT_Q + wm + g;
                const int grow1 = grow0 + 8;
#pragma unroll
                for (int nt = 0; nt < 8; nt++) {
                    const int gc0 = kt * AT_K + nt * 8 + 2 * tg;
                    if (gc0     > grow0) s[nt][0] = NEG_INF_F;
                    if (gc0 + 1 > grow0) s[nt][1] = NEG_INF_F;
                    if (gc0     > grow1) s[nt][2] = NEG_INF_F;
                    if (gc0 + 1 > grow1) s[nt][3] = NEG_INF_F;
                }
            }

            // ---- p = 2^s directly in fp16 ----
            __half2 p01[8], p23[8];
#pragma unroll
            for (int nt = 0; nt < 8; nt++) {
                p01[nt] = h2exp2(__floats2half2_rn(s[nt][0], s[nt][1]));
                p23[nt] = h2exp2(__floats2half2_rn(s[nt][2], s[nt][3]));
            }

            // ---- l partials on the fma pipe ----
            {
                __half2 t0 = __hadd2(p01[0], p01[1]);
                __half2 t1 = __hadd2(p01[2], p01[3]);
                __half2 t2 = __hadd2(p01[4], p01[5]);
                __half2 t3 = __hadd2(p01[6], p01[7]);
                t0 = __hadd2(__hadd2(t0, t1), __hadd2(t2, t3));
                float2 f = __half22float2(t0);
                lsum0 += f.x + f.y;
                __half2 u0 = __hadd2(p23[0], p23[1]);
                __half2 u1 = __hadd2(p23[2], p23[3]);
                __half2 u2 = __hadd2(p23[4], p23[5]);
                __half2 u3 = __hadd2(p23[6], p23[7]);
                u0 = __hadd2(__hadd2(u0, u1), __hadd2(u2, u3));
                float2 fu = __half22float2(u0);
                lsum1 += fu.x + fu.y;
            }

            // ---- O += P @ V ----
#pragma unroll
            for (int s4 = 0; s4 < 4; s4++) {
                const int ko = s4 * 16;
                const uint32_t a0 = h2_u32(p01[2 * s4]);
                const uint32_t a1 = h2_u32(p23[2 * s4]);
                const uint32_t a2 = h2_u32(p01[2 * s4 + 1]);
                const uint32_t a3 = h2_u32(p23[2 * s4 + 1]);
#pragma unroll
                for (int ntp = 0; ntp < 4; ntp++) {
                    uint32_t vb[4];
                    ldsm_x4_t(vb, Vb + (uint32_t)((ko + vrow) * HS + ntp * 16 + vcol) * 2);
                    mma_f16(o[2 * ntp],     a0, a1, a2, a3, vb[0], vb[1]);
                    mma_f16(o[2 * ntp + 1], a0, a1, a2, a3, vb[2], vb[3]);
                }
            }
        }

        buf = (buf + 1 == NBUF) ? 0 : buf + 1;
    }

    // ---- epilogue ----
    float l0 = lsum0 + __shfl_xor_sync(0xffffffffu, lsum0, 1);
    l0 += __shfl_xor_sync(0xffffffffu, l0, 2);
    float l1 = lsum1 + __shfl_xor_sync(0xffffffffu, lsum1, 1);
    l1 += __shfl_xor_sync(0xffffffffu, l1, 2);
    const float inv0 = 1.f / l0;
    const float inv1 = 1.f / l1;
    const size_t row0 = (size_t)(btok + qt * AT_Q + wm + g);
#pragma unroll
    for (int nt = 0; nt < 8; nt++) {
        const int col = h * DH_ + nt * 8 + 2 * tg;
        *(__half2*)&attn[row0 * D_ + col] =
            __floats2half2_rn(o[nt][0] * inv0, o[nt][1] * inv0);
        *(__half2*)&attn[(row0 + 8) * D_ + col] =
            __floats2half2_rn(o[nt][2] * inv1, o[nt][3] * inv1);
    }
}

// ---------------------------------------------------------------------------
// Launch
// ---------------------------------------------------------------------------
extern "C" void kernel_launch(void* const* d_in, const int* in_sizes, int n_in,
                              void* d_out, int out_size)
{
    const float* x     = (const float*)d_in[0];
    const float* w_qkv = (const float*)d_in[1];
    const float* w_out = (const float*)d_in[2];
    float* out = (float*)d_out;

    __half *xh, *wqh, *woh, *qkvh, *ath;
    cudaGetSymbolAddress((void**)&xh,   g_x);
    cudaGetSymbolAddress((void**)&wqh,  g_wqkv);
    cudaGetSymbolAddress((void**)&woh,  g_wout);
    cudaGetSymbolAddress((void**)&qkvh, g_qkv);
    cudaGetSymbolAddress((void**)&ath,  g_attn);

    // 0) fused fp32->fp16 conversion (one launch)
    cvt_all_kernel<<<1184, 256>>>(x, w_qkv, w_out, xh, wqh, woh);

    // 1) QKV projection (fp32-acc; at HMMA floor); Q pre-scaled by 0.125*log2e
    {
        cudaFuncSetAttribute(gemm_f16_kernel<false>,
                             cudaFuncAttributeMaxDynamicSharedMemorySize,
                             (int)GEMM_SMEM);
        dim3 grid(3 * D_ / GBN, M_TOK / GBM);
        gemm_f16_kernel<false><<<grid, 256, GEMM_SMEM>>>(
            xh, wqh, nullptr, qkvh, M_TOK, 3 * D_, D_, 1);
    }

    // 2) Flash attention (fp16 TC, warp tile-skip, 5-buffer ring)
    {
        cudaFuncSetAttribute(attn_kernel,
                             cudaFuncAttributeMaxDynamicSharedMemorySize,
                             (int)ATTN_SMEM);
        dim3 grid(S_ / AT_Q, H_, B_);
        attn_kernel<<<grid, 256, ATTN_SMEM>>>(qkvh, ath);
    }

    // 3) Output projection — fp16-accumulate PROBE (per-stage fp32 promotion)
    {
        cudaFuncSetAttribute(gemm_f16_kernel<true>,
                             cudaFuncAttributeMaxDynamicSharedMemorySize,
                             (int)GEMM_SMEM);
        dim3 grid(D_ / GBN, M_TOK / GBM);
        gemm_f16_kernel<true><<<grid, 256, GEMM_SMEM>>>(
            ath, woh, out, nullptr, M_TOK, D_, D_, 0);
    }
}